// round 17
// baseline (speedup 1.0000x reference)
#include <cuda_runtime.h>
#include <cuda_fp16.h>
#include <cstdint>

// ---------------- problem constants ----------------
#define Bn    128
#define Hn    12
#define Nn    100
#define HPC   4              // heads per CTA
#define CL    3              // CTAs per cluster (HPC*CL == Hn)
#define WPH   2              // warps per head
#define NW    (HPC*WPH)      // 8 warps per CTA
#define NT    (NW*32)        // 256 threads
#define ITERS 500

#define GAMMA_ 5.0f
#define COST_  1e-3f
#define KAPPA_ 2.0627128075074256f
#define PEN_   100.0f
#define LR_    0.01f

// Pair-interleaved G: per head 50 row-pairs x 25 lane-slabs x 8 halfs = 10000 halfs
#define GH_HALF   10000
#define G_BYTES   (HPC*GH_HALF*2)              // 80000
// SMEM layout (bytes)
#define WBUF_BYTE G_BYTES                      // fp32 w: [2][HPC][128] = 4096
#define WDUP_BYTE (WBUF_BYTE + 2*HPC*128*4)    // dup-pair w: [2][HPC][200] f32 = 6400
#define PA_BYTE   (WDUP_BYTE + 2*HPC*200*4)    // partial-a: [NW][128] f32 = 4096
#define MB_BYTE   (PA_BYTE + NW*128*4)         // 2 mbarriers
#define SMEM_BYTES (MB_BYTE + 16)              // 94608 B -> 2 CTAs/SM

// Scratch for pair-interleaved fp16 G (~31 MB)
__device__ __half g_G[(size_t)Bn * Hn * GH_HALF];

// ---------------------------------------------------------------------------
// Precompute G[b,h] = L L^T (fp32 accumulate, fp16 store, pair-interleaved)
// slot(j_row, i_col) = (j>>1)*200 + (i>>2)*8 + (j&1)*4 + (i&3)
// ---------------------------------------------------------------------------
__global__ __launch_bounds__(256) void precompute_G(const float* __restrict__ L) {
    __shared__ __align__(16) float Ls[Nn * Nn];
    const int bh = blockIdx.x;
    const float4* src = (const float4*)(L + (size_t)bh * Nn * Nn);
    float4* d4 = (float4*)Ls;
    for (int i = threadIdx.x; i < Nn * Nn / 4; i += blockDim.x) d4[i] = src[i];
    __syncthreads();
    __half* outp = g_G + (size_t)bh * GH_HALF;
    for (int idx = threadIdx.x; idx < Nn * Nn; idx += blockDim.x) {
        const int j = idx / Nn;       // input row
        const int i = idx - j * Nn;   // output col
        const float4* ra = (const float4*)(Ls + j * Nn);
        const float4* rb = (const float4*)(Ls + i * Nn);
        float a0 = 0.f, a1 = 0.f, a2 = 0.f, a3 = 0.f;
#pragma unroll
        for (int m = 0; m < Nn / 4; m++) {
            float4 x = ra[m], y = rb[m];
            a0 = fmaf(x.x, y.x, a0);
            a1 = fmaf(x.y, y.y, a1);
            a2 = fmaf(x.z, y.z, a2);
            a3 = fmaf(x.w, y.w, a3);
        }
        float r = (a0 + a1) + (a2 + a3);
        int slot = (j >> 1) * 200 + (i >> 2) * 8 + (j & 1) * 4 + (i & 3);
        outp[slot] = __float2half_rn(r);
    }
}

// ---------------------------------------------------------------------------
// Helpers
// ---------------------------------------------------------------------------
__device__ __forceinline__ float red1(float x) {
#pragma unroll
    for (int o = 16; o; o >>= 1) x += __shfl_xor_sync(0xffffffffu, x, o);
    return x;
}

__device__ __forceinline__ void red2(float& x, float& y) {
#pragma unroll
    for (int o = 16; o; o >>= 1) {
        x += __shfl_xor_sync(0xffffffffu, x, o);
        y += __shfl_xor_sync(0xffffffffu, y, o);
    }
}

__device__ __forceinline__ void red4(float& x, float& y, float& z, float& w) {
#pragma unroll
    for (int o = 16; o; o >>= 1) {
        x += __shfl_xor_sync(0xffffffffu, x, o);
        y += __shfl_xor_sync(0xffffffffu, y, o);
        z += __shfl_xor_sync(0xffffffffu, z, o);
        w += __shfl_xor_sync(0xffffffffu, w, o);
    }
}

// Packed f32x2 FMA (SASS FFMA2) — only reachable via PTX fma.rn.f32x2.
__device__ __forceinline__ void ffma2(unsigned long long& acc,
                                      unsigned long long a, unsigned long long b) {
    asm("fma.rn.f32x2 %0, %1, %2, %0;" : "+l"(acc) : "l"(a), "l"(b));
}
// f16x2 bits -> f32x2 bits (2 scalar converts + pack; pack usually elided)
__device__ __forceinline__ unsigned long long h2f2(uint32_t hbits) {
    __half2 hh;
    *reinterpret_cast<uint32_t*>(&hh) = hbits;
    float2 f = __half22float2(hh);
    unsigned long long r;
    asm("mov.b64 %0, {%1, %2};" : "=l"(r) : "f"(f.x), "f"(f.y));
    return r;
}
__device__ __forceinline__ float2 f2unpack(unsigned long long v) {
    float2 f;
    asm("mov.b64 {%0, %1}, %2;" : "=f"(f.x), "=f"(f.y) : "l"(v));
    return f;
}

#define CLUSTER_SYNC_() \
    asm volatile("barrier.cluster.arrive.aligned;\n\tbarrier.cluster.wait.aligned;" ::: "memory")

#define PAIR_BAR_(id) \
    asm volatile("bar.sync %0, 64;" :: "r"(id) : "memory")

__device__ __forceinline__ void mbar_wait_cluster(uint32_t addr, uint32_t par) {
    asm volatile(
        "{\n\t.reg .pred P;\n\t"
        "WAITL_%=:\n\t"
        "mbarrier.try_wait.parity.acquire.cluster.shared::cta.b64 P, [%0], %1, 0x989680;\n\t"
        "@P bra.uni WD_%=;\n\t"
        "bra.uni WAITL_%=;\n\t"
        "WD_%=:\n\t}"
        :: "r"(addr), "r"(par) : "memory");
}

__device__ __forceinline__ void mbar_arrive_remote(uint32_t remote_addr) {
    asm volatile(
        "mbarrier.arrive.release.cluster.shared::cluster.b64 _, [%0];"
        :: "r"(remote_addr) : "memory");
}

// ---------------------------------------------------------------------------
// Solver: cluster of 3 CTAs per batch; CTA rank r owns heads 4r..4r+3,
// two warps per head. fp16 G (pair-interleaved) in SMEM; fp32 FFMA2 math.
// Neighbor mbarrier handshakes for cross-CTA sync.
// ---------------------------------------------------------------------------
__global__ __cluster_dims__(CL, 1, 1) __launch_bounds__(NT, 2)
void solve_kernel(const float* __restrict__ mu, const float* __restrict__ wprev,
                  const float* __restrict__ lim, float* __restrict__ out)
{
    extern __shared__ __align__(16) char smraw[];
    __half* Gs   = (__half*)smraw;                 // [HPC][10000] fp16 pair-interleaved
    float*  wbuf = (float*)(smraw + WBUF_BYTE);    // [2][HPC][128] fp32
    float*  wdup = (float*)(smraw + WDUP_BYTE);    // [2][HPC][200] fp32 dup pairs
    float*  pa   = (float*)(smraw + PA_BYTE);      // [NW][128] partial-a

    const int tid  = threadIdx.x;
    const int lane = tid & 31;
    const int warp = tid >> 5;            // 0..7
    const int head = warp & (HPC - 1);    // head within CTA
    const int half = warp >> 2;           // 0: pairs [0,26), 1: pairs [26,50)
    uint32_t rank;
    asm("mov.u32 %0, %%cluster_ctarank;" : "=r"(rank));
    const int  b   = blockIdx.x / CL;
    const int  h   = HPC * (int)rank + head;
    const int  bh  = b * Hn + h;
    const bool vlane = (lane < 25);       // 25 lanes x 4 elems = 100
    const int  lv  = vlane ? lane : 24;   // clamped lane for safe addresses

    const uint32_t smem_u32 = (uint32_t)__cvta_generic_to_shared(smraw);
    const uint32_t mb0 = smem_u32 + MB_BYTE;      // full[0]
    const uint32_t mb1 = mb0 + 8;                 // full[1]
    const bool has_lo = (rank > 0);
    const bool has_hi = (rank + 1 < CL);

    // Load this CTA's 4 fp16 G matrices into SMEM (contiguous in g_G)
    {
        const uint4* s4 = (const uint4*)(g_G + (size_t)(b * Hn + HPC * (int)rank) * GH_HALF);
        uint4* d4 = (uint4*)Gs;
        const int n4 = G_BYTES / 16;
        for (int i = tid; i < n4; i += NT) d4[i] = s4[i];
    }
    // Init plain w buffers (zero pads)
    for (int i = tid; i < 2 * HPC * 128; i += NT) {
        int e = i & 127;
        wbuf[i] = (e < Nn) ? wprev[(size_t)b * Nn + e] : 0.0f;
    }
    // Init duplicated-pair w buffers
    for (int i = tid; i < 2 * HPC * Nn; i += NT) {
        int e = i % Nn;
        float v = wprev[(size_t)b * Nn + e];
        int base = (i / Nn) * 200;
        wdup[base + 2 * e]     = v;
        wdup[base + 2 * e + 1] = v;
    }
    // Init neighbor-handshake mbarriers
    if (tid == 0) {
        const uint32_t n_nb = (uint32_t)((has_lo ? 1 : 0) + (has_hi ? 1 : 0));
        asm volatile("mbarrier.init.shared.b64 [%0], %1;" :: "r"(mb0), "r"(n_nb) : "memory");
        asm volatile("mbarrier.init.shared.b64 [%0], %1;" :: "r"(mb1), "r"(n_nb) : "memory");
    }

    // Per-lane registers
    float4 mu4, w4, wlag0;
    {
        const float4* mp = (const float4*)(mu + (size_t)bh * Nn);
        const float4* pp = (const float4*)(wprev + (size_t)b * Nn);
        float4 m = mp[lv], p = pp[lv];
        if (!vlane) { m = make_float4(0, 0, 0, 0); p = make_float4(0, 0, 0, 0); }
        mu4 = m; w4 = p; wlag0 = p;
    }
    const float SUM_MU = red1(vlane ? (mu4.x + mu4.y + mu4.z + mu4.w) : 0.0f);

    const float limb    = lim[b];
    const bool  h_first = (h == 0);
    const bool  h_last  = (h == Hn - 1);
    const float fnext   = h_last ? 0.0f : 1.0f;
    const bool remote_rd = (head == 0 && has_lo) || (head == HPC - 1 && has_hi);

    // DSMEM addresses for boundary reads + remote arrivals
    uint32_t ra_lag[2], ra_next[2];
    uint32_t arr_lo0 = 0, arr_lo1 = 0, arr_hi0 = 0, arr_hi1 = 0;
    {
        uint32_t wbase = (uint32_t)__cvta_generic_to_shared(wbuf);
        uint32_t rlo = has_lo ? (rank - 1) : 0u;
        uint32_t rhi = has_hi ? (rank + 1) : rank;
#pragma unroll
        for (int bu = 0; bu < 2; bu++) {
            uint32_t off_lag  = wbase + (uint32_t)(((bu * HPC + (HPC - 1)) * 128 + 4 * lv) * 4);
            uint32_t off_next = wbase + (uint32_t)(((bu * HPC + 0) * 128 + 4 * lv) * 4);
            asm("mapa.shared::cluster.u32 %0, %1, %2;" : "=r"(ra_lag[bu])  : "r"(off_lag),  "r"(rlo));
            asm("mapa.shared::cluster.u32 %0, %1, %2;" : "=r"(ra_next[bu]) : "r"(off_next), "r"(rhi));
        }
        asm("mapa.shared::cluster.u32 %0, %1, %2;" : "=r"(arr_lo0) : "r"(mb0), "r"(rlo));
        asm("mapa.shared::cluster.u32 %0, %1, %2;" : "=r"(arr_lo1) : "r"(mb1), "r"(rlo));
        asm("mapa.shared::cluster.u32 %0, %1, %2;" : "=r"(arr_hi0) : "r"(mb0), "r"(rhi));
        asm("mapa.shared::cluster.u32 %0, %1, %2;" : "=r"(arr_hi1) : "r"(mb1), "r"(rhi));
    }

    CLUSTER_SYNC_();   // publish G + initial w + mbarrier init to whole cluster

    const __half* Gl = Gs + head * GH_HALF + lv * 8;   // lane's slab base
    float* paw       = pa + warp * 128;                // own partial slot
    const float* pao = pa + (warp ^ 4) * 128 + 4 * lv; // pair's partial slot
    const int pp0 = half ? 26 : 0;                     // row-pair range
    const int pp1 = half ? 50 : 26;
    const int barid = 1 + head;

    for (int it = 0; it < ITERS; it++) {
        const int cur = it & 1;

        // --- handshake: remote-reading warps wait for neighbor publish ---
        if (it > 0 && remote_rd) {
            mbar_wait_cluster(cur ? mb1 : mb0, (uint32_t)(((it - 1) >> 1) & 1));
        }

        // --- neighbor reads (issued early; latency hidden by matvec) ---
        float4 wlag4, wnext4;
        if (h_first) {
            wlag4 = wlag0;
        } else if (head > 0) {
            wlag4 = *(const float4*)(wbuf + (cur * HPC + head - 1) * 128 + 4 * lv);
        } else {
            asm volatile("ld.shared::cluster.v4.f32 {%0,%1,%2,%3}, [%4];"
                         : "=f"(wlag4.x), "=f"(wlag4.y), "=f"(wlag4.z), "=f"(wlag4.w)
                         : "r"(ra_lag[cur]));
        }
        if (h_last) {
            wnext4 = make_float4(0, 0, 0, 0);
        } else if (head < HPC - 1) {
            wnext4 = *(const float4*)(wbuf + (cur * HPC + head + 1) * 128 + 4 * lv);
        } else {
            asm volatile("ld.shared::cluster.v4.f32 {%0,%1,%2,%3}, [%4];"
                         : "=f"(wnext4.x), "=f"(wnext4.y), "=f"(wnext4.z), "=f"(wnext4.w)
                         : "r"(ra_next[cur]));
        }

        // --- partial a = G w over this warp's row-pair range ---
        // FFMA2 packed-fp32 math; G pair-interleaved (LDS.128 per 2 rows).
        const ulonglong2* Wd =
            (const ulonglong2*)(wdup + (cur * HPC + head) * 200);
        unsigned long long aA01 = 0ull, aA23 = 0ull;
        unsigned long long aB01 = 0ull, aB23 = 0ull;
#pragma unroll 4
        for (int p = pp0; p < pp1; p += 2) {
            uint4 ga = *(const uint4*)(Gl + (size_t)p * 200);
            uint4 gb = *(const uint4*)(Gl + (size_t)(p + 1) * 200);
            ulonglong2 wa = Wd[p];
            ulonglong2 wb = Wd[p + 1];
            ffma2(aA01, h2f2(ga.x), wa.x);   // row 2p   -> outs 4lv,4lv+1
            ffma2(aA23, h2f2(ga.y), wa.x);   // row 2p   -> outs 4lv+2,4lv+3
            ffma2(aA01, h2f2(ga.z), wa.y);   // row 2p+1
            ffma2(aA23, h2f2(ga.w), wa.y);
            ffma2(aB01, h2f2(gb.x), wb.x);   // row 2p+2
            ffma2(aB23, h2f2(gb.y), wb.x);
            ffma2(aB01, h2f2(gb.z), wb.y);   // row 2p+3
            ffma2(aB23, h2f2(gb.w), wb.y);
        }
        float4 aP;
        {
            float2 a01 = f2unpack(aA01), a23 = f2unpack(aA23);
            float2 b01 = f2unpack(aB01), b23 = f2unpack(aB23);
            aP.x = a01.x + b01.x; aP.y = a01.y + b01.y;
            aP.z = a23.x + b23.x; aP.w = a23.y + b23.y;
        }

        // --- turnover (cost) terms; overlap with pair-combine wait ---
        float4 cst;
        {
            float d;
            d = w4.x - wlag4.x;  cst.x = COST_ * d * rsqrtf(fmaf(d, d, 1e-10f));
            d = wnext4.x - w4.x; cst.x -= fnext * COST_ * d * rsqrtf(fmaf(d, d, 1e-10f));
            d = w4.y - wlag4.y;  cst.y = COST_ * d * rsqrtf(fmaf(d, d, 1e-10f));
            d = wnext4.y - w4.y; cst.y -= fnext * COST_ * d * rsqrtf(fmaf(d, d, 1e-10f));
            d = w4.z - wlag4.z;  cst.z = COST_ * d * rsqrtf(fmaf(d, d, 1e-10f));
            d = wnext4.z - w4.z; cst.z -= fnext * COST_ * d * rsqrtf(fmaf(d, d, 1e-10f));
            d = w4.w - wlag4.w;  cst.w = COST_ * d * rsqrtf(fmaf(d, d, 1e-10f));
            d = wnext4.w - w4.w; cst.w -= fnext * COST_ * d * rsqrtf(fmaf(d, d, 1e-10f));
        }

        // --- combine halves through SMEM scratch (per-head named barrier) ---
        if (vlane) *(float4*)(paw + 4 * lane) = aP;
        PAIR_BAR_(barid);
        float4 oth = *(const float4*)pao;
        float4 a4;
        a4.x = aP.x + oth.x; a4.y = aP.y + oth.y;
        a4.z = aP.z + oth.z; a4.w = aP.w + oth.w;

        // --- fused reductions: mu.w, w.Gw, sum(a), sum(cost) ---
        float p0 = mu4.x * w4.x + mu4.y * w4.y + mu4.z * w4.z + mu4.w * w4.w;
        float p1 = w4.x * a4.x + w4.y * a4.y + w4.z * a4.z + w4.w * a4.w;
        float p2 = vlane ? (a4.x + a4.y + a4.z + a4.w) : 0.0f;
        float p3 = vlane ? (cst.x + cst.y + cst.z + cst.w) : 0.0f;
        red4(p0, p1, p2, p3);
        const float s2      = p1 + 1e-12f;
        const float inv_sig = rsqrtf(s2);
        const float sigma   = s2 * inv_sig;
        const float zv      = KAPPA_ * sigma - p0 - limb;
        const float pen     = (zv > 0.0f) ? PEN_ : 0.0f;
        const float ca      = 2.0f * GAMMA_ + pen * KAPPA_ * inv_sig;
        const float cm      = -(1.0f + pen);

        // --- gradient + step: v = w - LR*(cm*mu + ca*a + cost) ---
        float4 v;
        v.x = w4.x - LR_ * (cm * mu4.x + ca * a4.x + cst.x);
        v.y = w4.y - LR_ * (cm * mu4.y + ca * a4.y + cst.y);
        v.z = w4.z - LR_ * (cm * mu4.z + ca * a4.z + cst.z);
        v.w = w4.w - LR_ * (cm * mu4.w + ca * a4.w + cst.w);
        if (!vlane) v = make_float4(-1e30f, -1e30f, -1e30f, -1e30f);

        // Algebraic Sum(v): Sum(w)=1 after projection.
        const float s0 = 1.0f - LR_ * (cm * SUM_MU + ca * p2 + p3);

        // --- exact simplex projection (Michelot) ---
        float kk    = 100.0f;
        float theta = (s0 - 1.0f) * 0.01f;
#pragma unroll 1
        for (int pass = 0; pass < 50; pass++) {
            float bs = 0.0f, bk = 0.0f;
            if (v.x > theta) { bs += v.x; bk += 1.0f; }
            if (v.y > theta) { bs += v.y; bk += 1.0f; }
            if (v.z > theta) { bs += v.z; bk += 1.0f; }
            if (v.w > theta) { bs += v.w; bk += 1.0f; }
            red2(bs, bk);
            if (bk == kk) break;
            kk = bk;
            theta = (bs - 1.0f) / bk;
        }
        w4.x = fmaxf(v.x - theta, 0.0f);
        w4.y = fmaxf(v.y - theta, 0.0f);
        w4.z = fmaxf(v.z - theta, 0.0f);
        w4.w = fmaxf(v.w - theta, 0.0f);

        // --- publish new w (plain + dup-pair); CTA-local sync; signal ---
        if (half == 0 && vlane) {
            const int nb = (cur ^ 1) * HPC + head;
            *(float4*)(wbuf + nb * 128 + 4 * lane) = w4;
            float* wd = wdup + nb * 200 + 8 * lane;
            *(float4*)(wd)     = make_float4(w4.x, w4.x, w4.y, w4.y);
            *(float4*)(wd + 4) = make_float4(w4.z, w4.z, w4.w, w4.w);
        }
        __syncthreads();
        if (tid == 0 && it + 1 < ITERS) {
            const int bp = cur ^ 1;
            if (has_lo) mbar_arrive_remote(bp ? arr_lo1 : arr_lo0);
            if (has_hi) mbar_arrive_remote(bp ? arr_hi1 : arr_hi0);
        }
    }

    if (half == 0 && vlane)
        *(float4*)(out + (size_t)bh * Nn + 4 * lane) = w4;

    // Keep cluster SMEM alive until all CTAs are done with DSMEM traffic.
    CLUSTER_SYNC_();
}

// ---------------------------------------------------------------------------
// Launch
// ---------------------------------------------------------------------------
extern "C" void kernel_launch(void* const* d_in, const int* in_sizes, int n_in,
                              void* d_out, int out_size) {
    const float *mu = nullptr, *L = nullptr, *wprev = nullptr, *lim = nullptr;
    for (int i = 0; i < n_in; i++) {
        switch (in_sizes[i]) {
            case Bn * Hn * Nn:       mu    = (const float*)d_in[i]; break;
            case Bn * Hn * Nn * Nn:  L     = (const float*)d_in[i]; break;
            case Bn * Nn:            wprev = (const float*)d_in[i]; break;
            case Bn:                 lim   = (const float*)d_in[i]; break;
            default: break;
        }
    }
    float* out = (float*)d_out;

    cudaFuncSetAttribute(solve_kernel, cudaFuncAttributeMaxDynamicSharedMemorySize, SMEM_BYTES);

    precompute_G<<<Bn * Hn, 256>>>(L);
    solve_kernel<<<Bn * CL, NT, SMEM_BYTES>>>(mu, wprev, lim, out);
}